// round 9
// baseline (speedup 1.0000x reference)
#include <cuda_runtime.h>
#include <cuda_bf16.h>

// Problem dims
#define SL 512   // sequence length L
#define NB 64    // batch
#define NE 256   // embed dim E
#define NH 256   // hidden H
#define NG 1024  // 4*H
#define NT 32    // tags T

// ---------------------------------------------------------------------------
// Device-global scratch (allocation is forbidden; __device__ arrays are the
// sanctioned workaround).
// ---------------------------------------------------------------------------
__device__ float    g_xproj[2][(size_t)SL * NB * NG];   // per-dir x_proj
__device__ float    g_hout [2][(size_t)SL * NB * NH];   // per-dir masked outputs
__device__ float    g_em   [(size_t)SL * NB * NT];      // emissions
__device__ float    g_hbuf [2][2][NB * NH];             // h broadcast, dbl-buffered
__device__ float    g_WoutT[512 * NT];                  // W_out transposed [k][t]
__device__ float    g_llh  [NB];
__device__ unsigned g_barcnt;
__device__ unsigned g_bargen;

// ---------------------------------------------------------------------------
// Software grid barrier (all LSTM blocks co-resident: 128 blocks, 1/SM via
// 168KB smem, 148 SMs -> wave-1 resident).
// ---------------------------------------------------------------------------
__device__ __forceinline__ void gridbar(unsigned nblocks) {
    __threadfence();          // release: make this thread's stores L2-visible
    __syncthreads();
    if (threadIdx.x == 0) {
        volatile unsigned* vgen = &g_bargen;
        unsigned gen = *vgen;
        unsigned t = atomicAdd(&g_barcnt, 1u);
        if (t == nblocks - 1u) {
            g_barcnt = 0u;
            __threadfence();
            *vgen = gen + 1u;
        } else {
            while (*vgen == gen) { }
        }
    }
    __syncthreads();
    __threadfence();          // acquire
}

// ---------------------------------------------------------------------------
// Kernel 1: x_proj[dir] = gather(embed, seqs) @ W_ih^T + (b_ih + b_hh)
// M=SL*NB rows, K=256, N=1024. Tile 64x64x16, 256 thr, 4x4 microtile.
// grid = (16, 512, 2)
// ---------------------------------------------------------------------------
__global__ __launch_bounds__(256) void xproj_kernel(
    const float* __restrict__ embed, const int* __restrict__ seqs,
    const float* __restrict__ Wf, const float* __restrict__ Wb,
    const float* __restrict__ bihf, const float* __restrict__ bhhf,
    const float* __restrict__ bihb, const float* __restrict__ bhhb)
{
    __shared__ float As[16][64];
    __shared__ float Bs[16][64];

    const int dir = blockIdx.z;
    const float* W  = dir ? Wb   : Wf;
    const float* b1 = dir ? bihb : bihf;
    const float* b2 = dir ? bhhb : bhhf;
    float* out = g_xproj[dir];

    const int tid = threadIdx.x;
    const int bn = blockIdx.x;          // N tile (0..15)
    const int bm = blockIdx.y;          // M tile (0..511)
    const int tx = tid & 15;            // n dir
    const int ty = tid >> 4;            // m dir
    const int lr = tid & 63;            // load row
    const int kq = (tid >> 6) * 4;      // load k offset {0,4,8,12}

    const long arow = (long)seqs[bm * 64 + lr] * 256;
    const float* Brow = W + (long)(bn * 64 + lr) * 256;

    float acc[4][4];
#pragma unroll
    for (int i = 0; i < 4; i++)
#pragma unroll
        for (int j = 0; j < 4; j++) acc[i][j] = 0.f;

    for (int k0 = 0; k0 < 256; k0 += 16) {
        float4 a = *(const float4*)(embed + arow + k0 + kq);
        float4 b = *(const float4*)(Brow + k0 + kq);
        __syncthreads();
        As[kq + 0][lr] = a.x; As[kq + 1][lr] = a.y;
        As[kq + 2][lr] = a.z; As[kq + 3][lr] = a.w;
        Bs[kq + 0][lr] = b.x; Bs[kq + 1][lr] = b.y;
        Bs[kq + 2][lr] = b.z; Bs[kq + 3][lr] = b.w;
        __syncthreads();
#pragma unroll
        for (int k = 0; k < 16; k++) {
            float4 av = *(const float4*)&As[k][ty * 4];
            float4 bv = *(const float4*)&Bs[k][tx * 4];
            float aa[4] = {av.x, av.y, av.z, av.w};
            float bb[4] = {bv.x, bv.y, bv.z, bv.w};
#pragma unroll
            for (int i = 0; i < 4; i++)
#pragma unroll
                for (int j = 0; j < 4; j++)
                    acc[i][j] = fmaf(aa[i], bb[j], acc[i][j]);
        }
    }

    const int ng = bn * 64 + tx * 4;
    float4 bias;
    bias.x = b1[ng + 0] + b2[ng + 0];
    bias.y = b1[ng + 1] + b2[ng + 1];
    bias.z = b1[ng + 2] + b2[ng + 2];
    bias.w = b1[ng + 3] + b2[ng + 3];
#pragma unroll
    for (int i = 0; i < 4; i++) {
        long r = (long)bm * 64 + ty * 4 + i;
        float4 o;
        o.x = acc[i][0] + bias.x;
        o.y = acc[i][1] + bias.y;
        o.z = acc[i][2] + bias.z;
        o.w = acc[i][3] + bias.w;
        *(float4*)(out + r * 1024 + ng) = o;
    }
}

// ---------------------------------------------------------------------------
// Kernel 2: persistent BiLSTM. 128 blocks (dir = blk>>6), 256 threads.
// Block covers 8 batches x 32 hidden. W_hh slice in XOR-swizzled smem
// (128KB); warps split K (32 each) with smem partial-sum reduction.
// h broadcast via double-buffered global (L2) + grid barrier per step.
// ---------------------------------------------------------------------------
#define LSTM_NBLK 128u
#define LSTM_SMEM_BYTES 172032  // (32768 + 8192 + 2048) floats

__global__ __launch_bounds__(256, 1) void lstm_kernel(
    const float* __restrict__ Whhf, const float* __restrict__ Whhb,
    const int* __restrict__ masks)
{
    extern __shared__ float sm[];
    float*  wsm  = sm;           // [128 rows][64 float4-chunks], XOR-swizzled
    float*  psum = sm + 32768;   // [8 warps][32 combos][32 lanes]
    float*  hsm  = sm + 40960;   // [8 b][256]
    float4* wsm4 = (float4*)wsm;
    float4* hsm4 = (float4*)hsm;

    const int tid  = threadIdx.x;
    const int w    = tid >> 5;
    const int lane = tid & 31;
    const int blk  = blockIdx.x;
    const int dir  = blk >> 6;
    const int sub  = blk & 63;
    const int b0   = (sub >> 3) * 8;   // batch octet base
    const int h0   = (sub & 7) * 32;   // hidden chunk base
    const int hh   = lane;             // update-phase hidden idx
    const int bb   = w;                // update-phase batch idx (0..7)

    const float* W  = dir ? Whhb : Whhf;
    const float* xp = g_xproj[dir];
    float* outp = g_hout[dir];

    // Load W_hh slice: rows (g*NH + h0 + hr), swizzle chunks by (hr & 7).
    for (int i = 0; i < 32; i++) {
        int idx = tid + i * 256;     // 0..8191 (float4 chunk index)
        int row = idx >> 6;          // 0..127 = g*32 + hr
        int cg  = idx & 63;
        int g   = row >> 5, hr = row & 31;
        float4 v = *(const float4*)(W + ((size_t)(g * 256 + h0 + hr)) * 256 + cg * 4);
        wsm4[row * 64 + (cg ^ (hr & 7))] = v;
    }
    // Zero initial h buffer (buffer 0); each (dir, b, h) covered exactly once.
    g_hbuf[dir][0][(b0 + bb) * 256 + h0 + hh] = 0.f;
    float hreg = 0.f, creg = 0.f;
    gridbar(LSTM_NBLK);

    const int xorm = lane & 7;
    int p = 0;
    for (int step = 0; step < 512; step++) {
        const int l = dir ? (511 - step) : step;

        // Prefetch gate pre-activations + mask (consumed ~4K cyc later).
        const float* xr = xp + ((size_t)(l * 64 + b0 + bb)) * 1024 + h0 + hh;
        float x0 = __ldg(xr + 0);
        float x1 = __ldg(xr + 256);
        float x2 = __ldg(xr + 512);
        float x3 = __ldg(xr + 768);
        int   m  = __ldg(masks + l * 64 + b0 + bb);

        // Stage h_prev (8 x 256) from L2 (bypass L1: cross-SM data).
        const float4* hb = (const float4*)g_hbuf[dir][p];
#pragma unroll
        for (int i = 0; i < 2; i++) {
            int idx = tid + i * 256;   // 0..511
            hsm4[idx] = __ldcg(hb + (b0 + (idx >> 6)) * 64 + (idx & 63));
        }
        __syncthreads();

        // GEMM: lane owns h' = h0+lane; warp owns k in [w*32, w*32+32).
        float acc[4][8];
#pragma unroll
        for (int g = 0; g < 4; g++)
#pragma unroll
            for (int b = 0; b < 8; b++) acc[g][b] = 0.f;

#pragma unroll 4
        for (int j = 0; j < 8; j++) {
            int cg = (w << 3) + j;
            int cs = cg ^ xorm;
            float4 wv0 = wsm4[(0 * 32 + lane) * 64 + cs];
            float4 wv1 = wsm4[(1 * 32 + lane) * 64 + cs];
            float4 wv2 = wsm4[(2 * 32 + lane) * 64 + cs];
            float4 wv3 = wsm4[(3 * 32 + lane) * 64 + cs];
#pragma unroll
            for (int b = 0; b < 8; b++) {
                float4 hv = hsm4[b * 64 + cg];
                acc[0][b] = fmaf(hv.x, wv0.x, acc[0][b]);
                acc[0][b] = fmaf(hv.y, wv0.y, acc[0][b]);
                acc[0][b] = fmaf(hv.z, wv0.z, acc[0][b]);
                acc[0][b] = fmaf(hv.w, wv0.w, acc[0][b]);
                acc[1][b] = fmaf(hv.x, wv1.x, acc[1][b]);
                acc[1][b] = fmaf(hv.y, wv1.y, acc[1][b]);
                acc[1][b] = fmaf(hv.z, wv1.z, acc[1][b]);
                acc[1][b] = fmaf(hv.w, wv1.w, acc[1][b]);
                acc[2][b] = fmaf(hv.x, wv2.x, acc[2][b]);
                acc[2][b] = fmaf(hv.y, wv2.y, acc[2][b]);
                acc[2][b] = fmaf(hv.z, wv2.z, acc[2][b]);
                acc[2][b] = fmaf(hv.w, wv2.w, acc[2][b]);
                acc[3][b] = fmaf(hv.x, wv3.x, acc[3][b]);
                acc[3][b] = fmaf(hv.y, wv3.y, acc[3][b]);
                acc[3][b] = fmaf(hv.z, wv3.z, acc[3][b]);
                acc[3][b] = fmaf(hv.w, wv3.w, acc[3][b]);
            }
        }

        // Write K-partials.
#pragma unroll
        for (int g = 0; g < 4; g++)
#pragma unroll
            for (int b = 0; b < 8; b++)
                psum[w * 1024 + (g * 8 + b) * 32 + lane] = acc[g][b];
        __syncthreads();

        // Reduce across warps; thread = (bb, hh).
        float s0 = 0.f, s1 = 0.f, s2 = 0.f, s3 = 0.f;
#pragma unroll
        for (int ww = 0; ww < 8; ww++) {
            s0 += psum[ww * 1024 + (0 * 8 + bb) * 32 + hh];
            s1 += psum[ww * 1024 + (1 * 8 + bb) * 32 + hh];
            s2 += psum[ww * 1024 + (2 * 8 + bb) * 32 + hh];
            s3 += psum[ww * 1024 + (3 * 8 + bb) * 32 + hh];
        }

        float gi = 1.f / (1.f + __expf(-(x0 + s0)));
        float gf = 1.f / (1.f + __expf(-(x1 + s1)));
        float gg = tanhf(x2 + s2);
        float go = 1.f / (1.f + __expf(-(x3 + s3)));
        float cn = gf * creg + gi * gg;
        float hn = go * tanhf(cn);
        float outv;
        if (m) { creg = cn; hreg = hn; outv = hn; } else { outv = 0.f; }

        outp[((size_t)(l * 64 + b0 + bb)) * 256 + h0 + hh] = outv;
        g_hbuf[dir][p ^ 1][(b0 + bb) * 256 + h0 + hh] = hreg;

        gridbar(LSTM_NBLK);
        p ^= 1;
    }
}

// ---------------------------------------------------------------------------
// Kernel 3a: transpose W_out (T,512) -> g_WoutT (512,T). One-time, tiny.
// ---------------------------------------------------------------------------
__global__ void wtrans_kernel(const float* __restrict__ Wout) {
    int idx = blockIdx.x * 256 + threadIdx.x;
    if (idx < 512 * NT) {
        int k = idx >> 5, t = idx & 31;
        g_WoutT[idx] = Wout[t * 512 + k];
    }
}

// ---------------------------------------------------------------------------
// Kernel 3b: emissions = [h_f | h_b] @ W_out^T + b_out.
// Block handles 8 rows x 32 tags; W_out^T and rows staged in smem.
// ---------------------------------------------------------------------------
#define EMIS_SMEM_BYTES 81920
__global__ __launch_bounds__(256) void emis_kernel(const float* __restrict__ bout)
{
    extern __shared__ float sm[];
    float* wsm = sm;            // [512 k][32 t]
    float* hsm = sm + 16384;    // [8 r][512]
    const int tid = threadIdx.x;
    const int bm = blockIdx.x;  // 0..4095

    for (int i = 0; i < 64; i++) {
        int idx = tid + i * 256;
        wsm[idx] = g_WoutT[idx];
    }
    for (int i = 0; i < 16; i++) {
        int idx = tid + i * 256;            // 0..4095
        int r = idx >> 9, k = idx & 511;
        size_t row = (size_t)bm * 8 + r;
        hsm[idx] = (k < 256) ? g_hout[0][row * 256 + k]
                             : g_hout[1][row * 256 + (k - 256)];
    }
    __syncthreads();

    const int r = tid >> 5, t = tid & 31;
    const float* hr = hsm + r * 512;
    float acc = bout[t];
#pragma unroll 8
    for (int k = 0; k < 512; k++)
        acc = fmaf(hr[k], wsm[k * 32 + t], acc);
    g_em[((size_t)bm * 8 + r) * 32 + t] = acc;
}

// ---------------------------------------------------------------------------
// Kernel 4: CRF. One warp per batch: 511 logsumexp steps (lane j = tag),
// plus numerator (lane-strided over l) and log_z, all in one kernel.
// ---------------------------------------------------------------------------
__global__ __launch_bounds__(32) void crf_kernel(
    const int* __restrict__ tags, const int* __restrict__ masks,
    const float* __restrict__ start_trans, const float* __restrict__ end_trans,
    const float* __restrict__ trans)
{
    __shared__ float tsm[NT * NT];
    const int b = blockIdx.x;
    const int j = threadIdx.x;

    for (int i = j; i < NT * NT; i += 32) tsm[i] = trans[i];
    __syncwarp();

    float score = start_trans[j] + g_em[(size_t)b * 32 + j];
    for (int l = 1; l < 512; l++) {
        float e = g_em[((size_t)(l * 64 + b)) * 32 + j];
        int   m = masks[l * 64 + b];
        float v[32];
        float mx = -3.4e38f;
#pragma unroll
        for (int i = 0; i < 32; i++) {
            v[i] = __shfl_sync(0xffffffffu, score, i) + tsm[i * 32 + j];
            mx = fmaxf(mx, v[i]);
        }
        float s = 0.f;
#pragma unroll
        for (int i = 0; i < 32; i++) s += __expf(v[i] - mx);
        float nxt = mx + __logf(s) + e;
        score = m ? nxt : score;
    }

    // Numerator (lane-strided over l) + lengths.
    float part = 0.f;
    int lenp = 0;
    for (int l = j; l < 512; l += 32) {
        int m = masks[l * 64 + b];
        lenp += m;
        int tg = tags[l * 64 + b];
        float e = g_em[((size_t)(l * 64 + b)) * 32 + tg];
        if (l == 0) {
            part += start_trans[tg] + e;
        } else {
            int tp = tags[(l - 1) * 64 + b];
            part += (e + tsm[tp * 32 + tg]) * (float)m;
        }
    }
#pragma unroll
    for (int off = 16; off > 0; off >>= 1) {
        part += __shfl_xor_sync(0xffffffffu, part, off);
        lenp += __shfl_xor_sync(0xffffffffu, lenp, off);
    }

    // log_z = LSE_j(score_j + end_trans_j)
    float tv = score + end_trans[j];
    float mx = tv;
#pragma unroll
    for (int off = 16; off > 0; off >>= 1)
        mx = fmaxf(mx, __shfl_xor_sync(0xffffffffu, mx, off));
    float ex = __expf(tv - mx);
#pragma unroll
    for (int off = 16; off > 0; off >>= 1)
        ex += __shfl_xor_sync(0xffffffffu, ex, off);
    float logz = mx + __logf(ex);

    if (j == 0) {
        int last = tags[(lenp - 1) * 64 + b];
        float num = part + end_trans[last];
        g_llh[b] = num - logz;
    }
}

// ---------------------------------------------------------------------------
// Kernel 5: final reduce: out = -mean(llh)
// ---------------------------------------------------------------------------
__global__ void final_kernel(float* __restrict__ out) {
    if (threadIdx.x == 0) {
        float s = 0.f;
        for (int i = 0; i < NB; i++) s += g_llh[i];
        out[0] = -s / (float)NB;
    }
}

// ---------------------------------------------------------------------------
extern "C" void kernel_launch(void* const* d_in, const int* in_sizes, int n_in,
                              void* d_out, int out_size) {
    const int*   seqs        = (const int*)d_in[0];
    const int*   tags        = (const int*)d_in[1];
    const int*   masks       = (const int*)d_in[2];
    const float* embed       = (const float*)d_in[3];
    const float* W_ih_f      = (const float*)d_in[4];
    const float* W_hh_f      = (const float*)d_in[5];
    const float* b_ih_f      = (const float*)d_in[6];
    const float* b_hh_f      = (const float*)d_in[7];
    const float* W_ih_b      = (const float*)d_in[8];
    const float* W_hh_b      = (const float*)d_in[9];
    const float* b_ih_b      = (const float*)d_in[10];
    const float* b_hh_b      = (const float*)d_in[11];
    const float* W_out       = (const float*)d_in[12];
    const float* b_out       = (const float*)d_in[13];
    const float* start_trans = (const float*)d_in[14];
    const float* end_trans   = (const float*)d_in[15];
    const float* trans       = (const float*)d_in[16];

    cudaFuncSetAttribute(lstm_kernel, cudaFuncAttributeMaxDynamicSharedMemorySize,
                         LSTM_SMEM_BYTES);
    cudaFuncSetAttribute(emis_kernel, cudaFuncAttributeMaxDynamicSharedMemorySize,
                         EMIS_SMEM_BYTES);

    dim3 xg(16, 512, 2);
    xproj_kernel<<<xg, 256>>>(embed, seqs, W_ih_f, W_ih_b,
                              b_ih_f, b_hh_f, b_ih_b, b_hh_b);
    wtrans_kernel<<<64, 256>>>(W_out);
    lstm_kernel<<<128, 256, LSTM_SMEM_BYTES>>>(W_hh_f, W_hh_b, masks);
    emis_kernel<<<4096, 256, EMIS_SMEM_BYTES>>>(b_out);
    crf_kernel<<<64, 32>>>(tags, masks, start_trans, end_trans, trans);
    final_kernel<<<1, 32>>>((float*)d_out);
}